// round 3
// baseline (speedup 1.0000x reference)
#include <cuda_runtime.h>
#include <math.h>

#define NN   16384
#define AA   16
#define FF   128
#define PI_F 3.14159265358979f
#define CUTI (PI_F / 5.0f)

// ---------------- scratch ----------------------------------------------------
__device__ float g_h  [NN * 128];
__device__ float g_phi[NN * 384];
__device__ float g_s1 [NN * 128];
__device__ float g_v1 [3 * NN * 128];
__device__ float g_Uv [3 * NN * 128];
__device__ float g_Vv [3 * NN * 128];
__device__ float g_x  [NN * 256];
__device__ float g_u  [NN * 128];
__device__ float g_m  [NN * 384];

// ---------------- packed f32x2 helpers ---------------------------------------
typedef unsigned long long u64;
__device__ __forceinline__ u64 pk2(float x, float y) {
    u64 r; asm("mov.b64 %0, {%1,%2};" : "=l"(r) : "f"(x), "f"(y)); return r;
}
__device__ __forceinline__ void upk2(float& x, float& y, u64 v) {
    asm("mov.b64 {%0,%1}, %2;" : "=f"(x), "=f"(y) : "l"(v));
}
__device__ __forceinline__ u64 fma2(u64 a, u64 b, u64 c) {
    u64 d; asm("fma.rn.f32x2 %0, %1, %2, %3;" : "=l"(d) : "l"(a), "l"(b), "l"(c)); return d;
}
__device__ __forceinline__ u64 mul2(u64 a, u64 b) {
    u64 d; asm("mul.rn.f32x2 %0, %1, %2;" : "=l"(d) : "l"(a), "l"(b)); return d;
}

// ---------------- SGEMM with packed f32x2 math --------------------------------
// C = act(A@B + bias). A: MxK (or gathered rows of embed), B: KxNc, both row-major.
// BM=BN=64, BK=16, 256 threads, 2x8 per-thread tile. act: 1 = silu.
// If aidx != nullptr, A row m is A[aidx[m]*K ...] (fused embedding gather).
__global__ void __launch_bounds__(256) k_gemm(
        const float* __restrict__ A, const int* __restrict__ aidx,
        const float* __restrict__ B, const float* __restrict__ bias,
        float* __restrict__ C, int K, int Nc, int act) {
    __shared__ float As[16][64];
    __shared__ __align__(16) float Bs[16][68];
    int t  = threadIdx.x;
    int m0 = blockIdx.x * 64, n0 = blockIdx.y * 64;
    int tx = t & 7,  ty = t >> 3;            // tx: 8 col-groups, ty: 32 row-pairs
    int am = t >> 2, ak = (t & 3) << 2;      // A stage
    int bk = t >> 4, bn = (t & 15) << 2;     // B stage
    u64 acc[2][4] = {};

    const float* Arow = aidx ? (A + (size_t)aidx[m0 + am] * K)
                             : (A + (size_t)(m0 + am) * K);

    for (int k0 = 0; k0 < K; k0 += 16) {
        float4 a = *(const float4*)(Arow + k0 + ak);
        As[ak + 0][am] = a.x; As[ak + 1][am] = a.y;
        As[ak + 2][am] = a.z; As[ak + 3][am] = a.w;
        *(float4*)&Bs[bk][bn] = *(const float4*)(B + (size_t)(k0 + bk) * Nc + n0 + bn);
        __syncthreads();
#pragma unroll
        for (int k = 0; k < 16; k++) {
            float2 av = *(const float2*)&As[k][ty * 2];
            u64 a0 = pk2(av.x, av.x);
            u64 a1 = pk2(av.y, av.y);
            ulonglong2 b01 = *(const ulonglong2*)&Bs[k][tx * 8];
            ulonglong2 b23 = *(const ulonglong2*)&Bs[k][tx * 8 + 4];
            acc[0][0] = fma2(a0, b01.x, acc[0][0]);
            acc[0][1] = fma2(a0, b01.y, acc[0][1]);
            acc[0][2] = fma2(a0, b23.x, acc[0][2]);
            acc[0][3] = fma2(a0, b23.y, acc[0][3]);
            acc[1][0] = fma2(a1, b01.x, acc[1][0]);
            acc[1][1] = fma2(a1, b01.y, acc[1][1]);
            acc[1][2] = fma2(a1, b23.x, acc[1][2]);
            acc[1][3] = fma2(a1, b23.y, acc[1][3]);
        }
        __syncthreads();
    }
#pragma unroll
    for (int r = 0; r < 2; r++) {
        float v[8];
#pragma unroll
        for (int q = 0; q < 4; q++) upk2(v[2 * q], v[2 * q + 1], acc[r][q]);
        float4 o0, o1;
        float* o = (float*)&o0;
#pragma unroll
        for (int j = 0; j < 8; j++) {
            float x = v[j] + bias[n0 + tx * 8 + j];
            if (act) x = x / (1.0f + __expf(-x));
            ((float*)&o0)[0] = ((float*)&o0)[0]; // keep compiler quiet
            if (j < 4) ((float*)&o0)[j] = x; else ((float*)&o1)[j - 4] = x;
        }
        (void)o;
        float* Crow = C + (size_t)(m0 + ty * 2 + r) * Nc + n0 + tx * 8;
        *(float4*)Crow       = o0;
        *(float4*)(Crow + 4) = o1;
    }
}

// ---------------- fused U/V GEMM: one launch for all 6 -----------------------
// grid (M/64, 4, 3): y<2 -> Uw/Uv, y>=2 -> Vw/Vv; z = plane k.
__global__ void __launch_bounds__(256) k_gemm_uv(
        const float* __restrict__ v1,
        const float* __restrict__ Uw, const float* __restrict__ Ub,
        const float* __restrict__ Vw, const float* __restrict__ Vb,
        float* __restrict__ Uv, float* __restrict__ Vv) {
    __shared__ float As[16][64];
    __shared__ __align__(16) float Bs[16][68];
    int t  = threadIdx.x;
    int zk = blockIdx.z;
    int isV = blockIdx.y >> 1;
    int m0 = blockIdx.x * 64, n0 = (blockIdx.y & 1) * 64;
    const float* A    = v1 + (size_t)zk * NN * 128;
    const float* B    = (isV ? Vw : Uw) + (size_t)zk * 128 * 128;
    const float* bias = (isV ? Vb : Ub) + zk * 128;
    float* C          = (isV ? Vv : Uv) + (size_t)zk * NN * 128;

    int tx = t & 7,  ty = t >> 3;
    int am = t >> 2, ak = (t & 3) << 2;
    int bk = t >> 4, bn = (t & 15) << 2;
    u64 acc[2][4] = {};

    for (int k0 = 0; k0 < 128; k0 += 16) {
        float4 a = *(const float4*)(A + (size_t)(m0 + am) * 128 + k0 + ak);
        As[ak + 0][am] = a.x; As[ak + 1][am] = a.y;
        As[ak + 2][am] = a.z; As[ak + 3][am] = a.w;
        *(float4*)&Bs[bk][bn] = *(const float4*)(B + (size_t)(k0 + bk) * 128 + n0 + bn);
        __syncthreads();
#pragma unroll
        for (int k = 0; k < 16; k++) {
            float2 av = *(const float2*)&As[k][ty * 2];
            u64 a0 = pk2(av.x, av.x);
            u64 a1 = pk2(av.y, av.y);
            ulonglong2 b01 = *(const ulonglong2*)&Bs[k][tx * 8];
            ulonglong2 b23 = *(const ulonglong2*)&Bs[k][tx * 8 + 4];
            acc[0][0] = fma2(a0, b01.x, acc[0][0]);
            acc[0][1] = fma2(a0, b01.y, acc[0][1]);
            acc[0][2] = fma2(a0, b23.x, acc[0][2]);
            acc[0][3] = fma2(a0, b23.y, acc[0][3]);
            acc[1][0] = fma2(a1, b01.x, acc[1][0]);
            acc[1][1] = fma2(a1, b01.y, acc[1][1]);
            acc[1][2] = fma2(a1, b23.x, acc[1][2]);
            acc[1][3] = fma2(a1, b23.y, acc[1][3]);
        }
        __syncthreads();
    }
#pragma unroll
    for (int r = 0; r < 2; r++) {
        float v[8];
#pragma unroll
        for (int q = 0; q < 4; q++) upk2(v[2 * q], v[2 * q + 1], acc[r][q]);
        float4 o0, o1;
#pragma unroll
        for (int j = 0; j < 4; j++) ((float*)&o0)[j] = v[j]     + bias[n0 + tx * 8 + j];
#pragma unroll
        for (int j = 0; j < 4; j++) ((float*)&o1)[j] = v[4 + j] + bias[n0 + tx * 8 + 4 + j];
        float* Crow = C + (size_t)(m0 + ty * 2 + r) * 128 + n0 + tx * 8;
        *(float4*)Crow       = o0;
        *(float4*)(Crow + 4) = o1;
    }
}

// ---------------- edge aggregation: one block per MOLECULE -------------------
// Exploits Wg(i,j) == Wg(j,i): only 120 unique pairs per molecule; self-edge
// contributes the constant cutoff(b_r) to s1 and nothing to v1.
__global__ void __launch_bounds__(256) k_edge(
        const float* __restrict__ pos, const float* __restrict__ phi,
        const float* __restrict__ w_r, const float* __restrict__ b_r,
        float* __restrict__ s1, float* __restrict__ v1) {
    __shared__ float posm[16][3];
    __shared__ float d_s[120];
    __shared__ float unit_s[120][3];
    __shared__ __align__(16) float rbf_s[120][20];
    int mol = blockIdx.x;
    int mb  = mol * 16;
    int t   = threadIdx.x;

    if (t < 48) posm[t / 3][t % 3] = pos[mb * 3 + t];
    __syncthreads();

    {   // unique pair distances + units
        int i = t >> 4, j = t & 15;
        if (i < j) {
            float rx = posm[i][0] - posm[j][0];
            float ry = posm[i][1] - posm[j][1];
            float rz = posm[i][2] - posm[j][2];
            float d  = sqrtf(rx * rx + ry * ry + rz * rz);
            float inv = 1.0f / (d + 1e-8f);
            int p = 15 * i - (i * (i - 1)) / 2 + (j - i - 1);
            d_s[p] = d;
            unit_s[p][0] = rx * inv; unit_s[p][1] = ry * inv; unit_s[p][2] = rz * inv;
        }
    }
    __syncthreads();

    for (int it = t; it < 2400; it += 256) {   // 120 pairs x 20 rbf
        int p = it / 20, k = it % 20;
        float d = d_s[p];
        rbf_s[p][k] = sinf((float)(k + 1) * CUTI * d) / (d + 1e-8f);
    }
    __syncthreads();

    int c = 128 + t;                            // lin_r column in [128,384)
    u64 wr2[10];
#pragma unroll
    for (int q = 0; q < 10; q++)
        wr2[q] = pk2(w_r[(2 * q) * 384 + c], w_r[(2 * q + 1) * 384 + c]);
    float brc = b_r[c];
    float wg0 = (brc < 5.0f) ? 0.5f * (cosf(brc * CUTI) + 1.0f) : 0.0f;  // self edge

    if (t < 128) {      // scalar (s1) columns
        float aS[16];
#pragma unroll
        for (int j = 0; j < 16; j++) aS[j] = wg0;
#pragma unroll
        for (int i = 0; i < 15; i++) {
#pragma unroll
            for (int j = i + 1; j < 16; j++) {
                int p = 15 * i - (i * (i - 1)) / 2 + (j - i - 1);
                const ulonglong2* r4 = (const ulonglong2*)rbf_s[p];
                u64 acc = mul2(wr2[0], r4[0].x);
                acc = fma2(wr2[1], r4[0].y, acc);
                ulonglong2 rA = r4[1], rB = r4[2], rC = r4[3], rD = r4[4];
                acc = fma2(wr2[2], rA.x, acc); acc = fma2(wr2[3], rA.y, acc);
                acc = fma2(wr2[4], rB.x, acc); acc = fma2(wr2[5], rB.y, acc);
                acc = fma2(wr2[6], rC.x, acc); acc = fma2(wr2[7], rC.y, acc);
                acc = fma2(wr2[8], rD.x, acc); acc = fma2(wr2[9], rD.y, acc);
                float lo, hi; upk2(lo, hi, acc);
                float lin = lo + hi + brc;
                float wg = (lin < 5.0f) ? 0.5f * (__cosf(lin * CUTI) + 1.0f) : 0.0f;
                aS[i] += wg; aS[j] += wg;
            }
        }
#pragma unroll
        for (int j = 0; j < 16; j++)
            s1[(size_t)(mb + j) * 128 + t] = phi[(size_t)(mb + j) * 384 + c] * aS[j];
    } else {            // vector (v1) columns
        int f = t - 128;
        float a0[16], a1[16], a2[16];
#pragma unroll
        for (int j = 0; j < 16; j++) { a0[j] = 0.f; a1[j] = 0.f; a2[j] = 0.f; }
#pragma unroll
        for (int i = 0; i < 15; i++) {
#pragma unroll
            for (int j = i + 1; j < 16; j++) {
                int p = 15 * i - (i * (i - 1)) / 2 + (j - i - 1);
                const ulonglong2* r4 = (const ulonglong2*)rbf_s[p];
                u64 acc = mul2(wr2[0], r4[0].x);
                acc = fma2(wr2[1], r4[0].y, acc);
                ulonglong2 rA = r4[1], rB = r4[2], rC = r4[3], rD = r4[4];
                acc = fma2(wr2[2], rA.x, acc); acc = fma2(wr2[3], rA.y, acc);
                acc = fma2(wr2[4], rB.x, acc); acc = fma2(wr2[5], rB.y, acc);
                acc = fma2(wr2[6], rC.x, acc); acc = fma2(wr2[7], rC.y, acc);
                acc = fma2(wr2[8], rD.x, acc); acc = fma2(wr2[9], rD.y, acc);
                float lo, hi; upk2(lo, hi, acc);
                float lin = lo + hi + brc;
                float wg = (lin < 5.0f) ? 0.5f * (__cosf(lin * CUTI) + 1.0f) : 0.0f;
                float u0 = unit_s[p][0], u1 = unit_s[p][1], u2 = unit_s[p][2];
                // pair (i<j): edge dest j gets +wg*unit, dest i gets -wg*unit
                a0[j] = fmaf(wg, u0, a0[j]);  a0[i] = fmaf(-wg, u0, a0[i]);
                a1[j] = fmaf(wg, u1, a1[j]);  a1[i] = fmaf(-wg, u1, a1[i]);
                a2[j] = fmaf(wg, u2, a2[j]);  a2[i] = fmaf(-wg, u2, a2[i]);
            }
        }
#pragma unroll
        for (int j = 0; j < 16; j++) {
            float p3 = phi[(size_t)(mb + j) * 384 + 256 + f];
            v1[(size_t)(0 * NN + mb + j) * 128 + f] = p3 * a0[j];
            v1[(size_t)(1 * NN + mb + j) * 128 + f] = p3 * a1[j];
            v1[(size_t)(2 * NN + mb + j) * 128 + f] = p3 * a2[j];
        }
    }
}

// ---------------- x = [ ||Vv|| | s1 ] -----------------------------------------
__global__ void k_buildx(const float* __restrict__ Vv,
                         const float* __restrict__ s1,
                         float* __restrict__ x) {
    int i = blockIdx.x * 256 + threadIdx.x;
    int n = i >> 7, f = i & 127;
    float v0 = Vv[i];
    float v1 = Vv[(size_t)NN * 128 + i];
    float v2 = Vv[(size_t)2 * NN * 128 + i];
    x[(size_t)n * 256 + f]       = sqrtf(v0 * v0 + v1 * v1 + v2 * v2);
    x[(size_t)n * 256 + 128 + f] = s1[i];
}

// ---------------- final epilogue -----------------------------------------------
__global__ void k_final(const float* __restrict__ m,
                        const float* __restrict__ Uv,
                        const float* __restrict__ Vv,
                        float* __restrict__ out) {
    __shared__ float dvs[768];
    int t = threadIdx.x;
    int i = blockIdx.x * 256 + t;
    int n = i >> 7, f = i & 127;
    float avv = m[(size_t)n * 384 + f];
    float asv = m[(size_t)n * 384 + 128 + f];
    float ass = m[(size_t)n * 384 + 256 + f];
    float u0 = Uv[i], u1 = Uv[(size_t)NN * 128 + i], u2 = Uv[(size_t)2 * NN * 128 + i];
    float v0 = Vv[i], v1 = Vv[(size_t)NN * 128 + i], v2 = Vv[(size_t)2 * NN * 128 + i];
    out[i] = (u0 * v0 + u1 * v1 + u2 * v2) * asv + ass;
    dvs[t * 3 + 0] = avv * u0;
    dvs[t * 3 + 1] = avv * u1;
    dvs[t * 3 + 2] = avv * u2;
    __syncthreads();
    size_t base = (size_t)NN * 128 + (size_t)blockIdx.x * 768;
    out[base + t]       = dvs[t];
    out[base + 256 + t] = dvs[256 + t];
    out[base + 512 + t] = dvs[512 + t];
}

// ---------------- launch --------------------------------------------------------
extern "C" void kernel_launch(void* const* d_in, const int* in_sizes, int n_in,
                              void* d_out, int out_size) {
    const int*   atoms = (const int*)  d_in[0];
    const float* pos   = (const float*)d_in[1];
    const float* embed = (const float*)d_in[4];
    const float* w_s1  = (const float*)d_in[5];
    const float* b_s1  = (const float*)d_in[6];
    const float* w_s2  = (const float*)d_in[7];
    const float* b_s2  = (const float*)d_in[8];
    const float* w_r   = (const float*)d_in[9];
    const float* b_r   = (const float*)d_in[10];
    const float* w_u1  = (const float*)d_in[11];
    const float* b_u1  = (const float*)d_in[12];
    const float* w_u2  = (const float*)d_in[13];
    const float* b_u2  = (const float*)d_in[14];
    const float* Uw    = (const float*)d_in[15];
    const float* Ub    = (const float*)d_in[16];
    const float* Vw    = (const float*)d_in[17];
    const float* Vb    = (const float*)d_in[18];
    float* out = (float*)d_out;

    float *h, *phi, *s1, *v1, *Uv, *Vv, *x, *u, *mm;
    cudaGetSymbolAddress((void**)&h,   g_h);
    cudaGetSymbolAddress((void**)&phi, g_phi);
    cudaGetSymbolAddress((void**)&s1,  g_s1);
    cudaGetSymbolAddress((void**)&v1,  g_v1);
    cudaGetSymbolAddress((void**)&Uv,  g_Uv);
    cudaGetSymbolAddress((void**)&Vv,  g_Vv);
    cudaGetSymbolAddress((void**)&x,   g_x);
    cudaGetSymbolAddress((void**)&u,   g_u);
    cudaGetSymbolAddress((void**)&mm,  g_m);

    // 1) h = silu(embed[atoms] @ w_s1 + b_s1)   (gather fused into A staging)
    k_gemm<<<dim3(NN / 64, 2), 256>>>(embed, atoms, w_s1, b_s1, h, 128, 128, 1);
    // 2) phi = h @ w_s2 + b_s2
    k_gemm<<<dim3(NN / 64, 6), 256>>>(h, nullptr, w_s2, b_s2, phi, 128, 384, 0);
    // 3) edge aggregation (one block per molecule)
    k_edge<<<NN / 16, 256>>>(pos, phi, w_r, b_r, s1, v1);
    // 4) all six U/V plane GEMMs in one launch
    k_gemm_uv<<<dim3(NN / 64, 4, 3), 256>>>(v1, Uw, Ub, Vw, Vb, Uv, Vv);
    // 5) x = [ ||Vv|| | s1 ]
    k_buildx<<<NN * 128 / 256, 256>>>(Vv, s1, x);
    // 6) u = silu(x @ w_u1 + b_u1)
    k_gemm<<<dim3(NN / 64, 2), 256>>>(x, nullptr, w_u1, b_u1, u, 256, 128, 1);
    // 7) m = u @ w_u2 + b_u2
    k_gemm<<<dim3(NN / 64, 6), 256>>>(u, nullptr, w_u2, b_u2, mm, 128, 384, 0);
    // 8) epilogue
    k_final<<<NN * 128 / 256, 256>>>(mm, Uv, Vv, out);
}

// round 4
// speedup vs baseline: 2.8785x; 2.8785x over previous
#include <cuda_runtime.h>
#include <math.h>
#include <stdint.h>

#define NN   16384
#define PI_F 3.14159265358979f
#define CUTI (PI_F / 5.0f)

// ---------------- scratch ----------------------------------------------------
__device__ float g_h  [NN * 128];
__device__ float g_phi[NN * 384];
__device__ float g_s1 [NN * 128];
__device__ float g_v1 [3 * NN * 128];
__device__ float g_Uv [3 * NN * 128];
__device__ float g_Vv [3 * NN * 128];
__device__ float g_x  [NN * 256];
__device__ float g_u  [NN * 128];
__device__ float g_m  [NN * 384];

// ---------------- packed f32x2 helpers (used by k_edge) -----------------------
typedef unsigned long long u64;
__device__ __forceinline__ u64 pk2(float x, float y) {
    u64 r; asm("mov.b64 %0, {%1,%2};" : "=l"(r) : "f"(x), "f"(y)); return r;
}
__device__ __forceinline__ void upk2(float& x, float& y, u64 v) {
    asm("mov.b64 {%0,%1}, %2;" : "=f"(x), "=f"(y) : "l"(v));
}
__device__ __forceinline__ u64 fma2(u64 a, u64 b, u64 c) {
    u64 d; asm("fma.rn.f32x2 %0, %1, %2, %3;" : "=l"(d) : "l"(a), "l"(b), "l"(c)); return d;
}
__device__ __forceinline__ u64 mul2(u64 a, u64 b) {
    u64 d; asm("mul.rn.f32x2 %0, %1, %2;" : "=l"(d) : "l"(a), "l"(b)); return d;
}

// ---------------- tf32 mma helpers --------------------------------------------
__device__ __forceinline__ uint32_t f2tf(float x) {
    uint32_t r; asm("cvt.rna.tf32.f32 %0, %1;" : "=r"(r) : "f"(x)); return r;
}
__device__ __forceinline__ uint32_t sptr(const void* p) {
    uint32_t r;
    asm("{ .reg .u64 t; cvta.to.shared.u64 t, %1; cvt.u32.u64 %0, t; }" : "=r"(r) : "l"(p));
    return r;
}
__device__ __forceinline__ void ldsm4(uint32_t& r0, uint32_t& r1, uint32_t& r2, uint32_t& r3,
                                      uint32_t addr) {
    asm volatile("ldmatrix.sync.aligned.m8n8.x4.shared.b16 {%0,%1,%2,%3}, [%4];"
                 : "=r"(r0), "=r"(r1), "=r"(r2), "=r"(r3) : "r"(addr));
}
__device__ __forceinline__ void mma_tf32(float& c0, float& c1, float& c2, float& c3,
                                         uint32_t a0, uint32_t a1, uint32_t a2, uint32_t a3,
                                         uint32_t b0, uint32_t b1) {
    asm volatile(
        "mma.sync.aligned.m16n8k8.row.col.f32.tf32.tf32.f32 "
        "{%0,%1,%2,%3}, {%4,%5,%6,%7}, {%8,%9}, {%0,%1,%2,%3};"
        : "+f"(c0), "+f"(c1), "+f"(c2), "+f"(c3)
        : "r"(a0), "r"(a1), "r"(a2), "r"(a3), "r"(b0), "r"(b1));
}

// ---------------- tf32 GEMM body: C = act(A@B + bias) --------------------------
// Block tile 128x64, BK=32, 128 threads = 4 warps (2m x 2n), warp tile 64x32.
// A: MxK row-major (optional row gather via aidx). B: KxN row-major (staged
// transposed n-major in smem). bias: N. act 1 = silu.
#define PITCH 36
__device__ __forceinline__ void gemm_body(
        const float* __restrict__ A, const int* __restrict__ aidx,
        const float* __restrict__ B, const float* __restrict__ bias,
        float* __restrict__ C, int K, int N, int act, int m0, int n0) {
    __shared__ __align__(16) uint32_t As[128 * PITCH];
    __shared__ __align__(16) uint32_t Bs[64 * PITCH];
    int t = threadIdx.x;
    int lane = t & 31, w = t >> 5;
    int wm = (w & 1) * 64, wn = (w >> 1) * 32;

    float acc[4][4][4] = {};

    uint32_t as_base = sptr(As), bs_base = sptr(Bs);
    int arow = (lane & 7) + ((lane >> 3) & 1) * 8;   // A-frag lane row
    int acol = (lane >> 4) * 4;                      // A-frag lane col
    int brow = (lane & 7) + (lane >> 4) * 8;         // B-frag lane row (n)
    int bcol = ((lane >> 3) & 1) * 4;                // B-frag lane col (k)

    for (int k0 = 0; k0 < K; k0 += 32) {
        // stage A (128x32) -> As[row][k], tf32-converted
#pragma unroll
        for (int i = 0; i < 8; i++) {
            int lin = t + i * 128;
            int row = lin >> 3, kc = (lin & 7) * 4;
            const float* src = aidx
                ? A + (size_t)aidx[m0 + row] * K + k0 + kc
                : A + (size_t)(m0 + row) * K + k0 + kc;
            float4 v = *(const float4*)src;
            uint4 uv;
            uv.x = f2tf(v.x); uv.y = f2tf(v.y); uv.z = f2tf(v.z); uv.w = f2tf(v.w);
            *(uint4*)&As[row * PITCH + kc] = uv;
        }
        // stage B (32x64) transposed -> Bs[n][k]
#pragma unroll
        for (int i = 0; i < 4; i++) {
            int lin = t + i * 128;
            int bk = lin & 31, bn = (lin >> 5) * 4;
            float4 v = *(const float4*)(B + (size_t)(k0 + bk) * N + n0 + bn);
            Bs[(bn + 0) * PITCH + bk] = f2tf(v.x);
            Bs[(bn + 1) * PITCH + bk] = f2tf(v.y);
            Bs[(bn + 2) * PITCH + bk] = f2tf(v.z);
            Bs[(bn + 3) * PITCH + bk] = f2tf(v.w);
        }
        __syncthreads();
#pragma unroll
        for (int ks = 0; ks < 4; ks++) {
            int kc = ks * 8;
            uint32_t a[4][4];
#pragma unroll
            for (int mt = 0; mt < 4; mt++) {
                uint32_t addr = as_base + ((wm + mt * 16 + arow) * PITCH + kc + acol) * 4;
                ldsm4(a[mt][0], a[mt][1], a[mt][2], a[mt][3], addr);
            }
            uint32_t b[4][2];
#pragma unroll
            for (int nh = 0; nh < 2; nh++) {
                uint32_t addr = bs_base + ((wn + nh * 16 + brow) * PITCH + kc + bcol) * 4;
                uint32_t r0, r1, r2, r3;
                ldsm4(r0, r1, r2, r3, addr);
                b[nh * 2][0] = r0;     b[nh * 2][1] = r1;
                b[nh * 2 + 1][0] = r2; b[nh * 2 + 1][1] = r3;
            }
#pragma unroll
            for (int mt = 0; mt < 4; mt++)
#pragma unroll
                for (int nt = 0; nt < 4; nt++)
                    mma_tf32(acc[mt][nt][0], acc[mt][nt][1], acc[mt][nt][2], acc[mt][nt][3],
                             a[mt][0], a[mt][1], a[mt][2], a[mt][3],
                             b[nt][0], b[nt][1]);
        }
        __syncthreads();
    }

    // epilogue
    int r = lane >> 2, c2 = (lane & 3) * 2;
#pragma unroll
    for (int mt = 0; mt < 4; mt++) {
        int row0 = m0 + wm + mt * 16 + r;
#pragma unroll
        for (int nt = 0; nt < 4; nt++) {
            int col = n0 + wn + nt * 8 + c2;
            float b0 = bias[col], b1 = bias[col + 1];
            float x0 = acc[mt][nt][0] + b0, x1 = acc[mt][nt][1] + b1;
            float x2 = acc[mt][nt][2] + b0, x3 = acc[mt][nt][3] + b1;
            if (act) {
                x0 = x0 / (1.0f + __expf(-x0));
                x1 = x1 / (1.0f + __expf(-x1));
                x2 = x2 / (1.0f + __expf(-x2));
                x3 = x3 / (1.0f + __expf(-x3));
            }
            float2 o0 = {x0, x1}, o1 = {x2, x3};
            *(float2*)(C + (size_t)row0 * N + col)       = o0;
            *(float2*)(C + (size_t)(row0 + 8) * N + col) = o1;
        }
    }
}

__global__ void __launch_bounds__(128) k_gemm_tf32(
        const float* __restrict__ A, const int* __restrict__ aidx,
        const float* __restrict__ B, const float* __restrict__ bias,
        float* __restrict__ C, int K, int N, int act) {
    gemm_body(A, aidx, B, bias, C, K, N, act, blockIdx.x * 128, blockIdx.y * 64);
}

// all 6 U/V plane GEMMs: grid (M/128, 2, 6); z<3 -> U plane z, z>=3 -> V plane z-3
__global__ void __launch_bounds__(128) k_gemm_uv_tf32(
        const float* __restrict__ v1,
        const float* __restrict__ Uw, const float* __restrict__ Ub,
        const float* __restrict__ Vw, const float* __restrict__ Vb,
        float* __restrict__ Uv, float* __restrict__ Vv) {
    int z = blockIdx.z;
    int isV = z >= 3;
    int k = isV ? z - 3 : z;
    const float* A    = v1 + (size_t)k * NN * 128;
    const float* B    = (isV ? Vw : Uw) + (size_t)k * 128 * 128;
    const float* bias = (isV ? Vb : Ub) + k * 128;
    float* C          = (isV ? Vv : Uv) + (size_t)k * NN * 128;
    gemm_body(A, nullptr, B, bias, C, 128, 128, 0, blockIdx.x * 128, blockIdx.y * 64);
}

// ---------------- edge aggregation: one block per MOLECULE -------------------
__global__ void __launch_bounds__(256) k_edge(
        const float* __restrict__ pos, const float* __restrict__ phi,
        const float* __restrict__ w_r, const float* __restrict__ b_r,
        float* __restrict__ s1, float* __restrict__ v1) {
    __shared__ float posm[16][3];
    __shared__ float d_s[120];
    __shared__ float unit_s[120][3];
    __shared__ __align__(16) float rbf_s[120][20];
    int mol = blockIdx.x;
    int mb  = mol * 16;
    int t   = threadIdx.x;

    if (t < 48) posm[t / 3][t % 3] = pos[mb * 3 + t];
    __syncthreads();

    {
        int i = t >> 4, j = t & 15;
        if (i < j) {
            float rx = posm[i][0] - posm[j][0];
            float ry = posm[i][1] - posm[j][1];
            float rz = posm[i][2] - posm[j][2];
            float d  = sqrtf(rx * rx + ry * ry + rz * rz);
            float inv = 1.0f / (d + 1e-8f);
            int p = 15 * i - (i * (i - 1)) / 2 + (j - i - 1);
            d_s[p] = d;
            unit_s[p][0] = rx * inv; unit_s[p][1] = ry * inv; unit_s[p][2] = rz * inv;
        }
    }
    __syncthreads();

    for (int it = t; it < 2400; it += 256) {
        int p = it / 20, k = it % 20;
        float d = d_s[p];
        rbf_s[p][k] = sinf((float)(k + 1) * CUTI * d) / (d + 1e-8f);
    }
    __syncthreads();

    int c = 128 + t;
    u64 wr2[10];
#pragma unroll
    for (int q = 0; q < 10; q++)
        wr2[q] = pk2(w_r[(2 * q) * 384 + c], w_r[(2 * q + 1) * 384 + c]);
    float brc = b_r[c];
    float wg0 = (brc < 5.0f) ? 0.5f * (cosf(brc * CUTI) + 1.0f) : 0.0f;

    if (t < 128) {
        float aS[16];
#pragma unroll
        for (int j = 0; j < 16; j++) aS[j] = wg0;
#pragma unroll
        for (int i = 0; i < 15; i++) {
#pragma unroll
            for (int j = i + 1; j < 16; j++) {
                int p = 15 * i - (i * (i - 1)) / 2 + (j - i - 1);
                const ulonglong2* r4 = (const ulonglong2*)rbf_s[p];
                u64 acc = mul2(wr2[0], r4[0].x);
                acc = fma2(wr2[1], r4[0].y, acc);
                ulonglong2 rA = r4[1], rB = r4[2], rC = r4[3], rD = r4[4];
                acc = fma2(wr2[2], rA.x, acc); acc = fma2(wr2[3], rA.y, acc);
                acc = fma2(wr2[4], rB.x, acc); acc = fma2(wr2[5], rB.y, acc);
                acc = fma2(wr2[6], rC.x, acc); acc = fma2(wr2[7], rC.y, acc);
                acc = fma2(wr2[8], rD.x, acc); acc = fma2(wr2[9], rD.y, acc);
                float lo, hi; upk2(lo, hi, acc);
                float lin = lo + hi + brc;
                float wg = (lin < 5.0f) ? 0.5f * (__cosf(lin * CUTI) + 1.0f) : 0.0f;
                aS[i] += wg; aS[j] += wg;
            }
        }
#pragma unroll
        for (int j = 0; j < 16; j++)
            s1[(size_t)(mb + j) * 128 + t] = phi[(size_t)(mb + j) * 384 + c] * aS[j];
    } else {
        int f = t - 128;
        float a0[16], a1[16], a2[16];
#pragma unroll
        for (int j = 0; j < 16; j++) { a0[j] = 0.f; a1[j] = 0.f; a2[j] = 0.f; }
#pragma unroll
        for (int i = 0; i < 15; i++) {
#pragma unroll
            for (int j = i + 1; j < 16; j++) {
                int p = 15 * i - (i * (i - 1)) / 2 + (j - i - 1);
                const ulonglong2* r4 = (const ulonglong2*)rbf_s[p];
                u64 acc = mul2(wr2[0], r4[0].x);
                acc = fma2(wr2[1], r4[0].y, acc);
                ulonglong2 rA = r4[1], rB = r4[2], rC = r4[3], rD = r4[4];
                acc = fma2(wr2[2], rA.x, acc); acc = fma2(wr2[3], rA.y, acc);
                acc = fma2(wr2[4], rB.x, acc); acc = fma2(wr2[5], rB.y, acc);
                acc = fma2(wr2[6], rC.x, acc); acc = fma2(wr2[7], rC.y, acc);
                acc = fma2(wr2[8], rD.x, acc); acc = fma2(wr2[9], rD.y, acc);
                float lo, hi; upk2(lo, hi, acc);
                float lin = lo + hi + brc;
                float wg = (lin < 5.0f) ? 0.5f * (__cosf(lin * CUTI) + 1.0f) : 0.0f;
                float u0 = unit_s[p][0], u1 = unit_s[p][1], u2 = unit_s[p][2];
                a0[j] = fmaf(wg, u0, a0[j]);  a0[i] = fmaf(-wg, u0, a0[i]);
                a1[j] = fmaf(wg, u1, a1[j]);  a1[i] = fmaf(-wg, u1, a1[i]);
                a2[j] = fmaf(wg, u2, a2[j]);  a2[i] = fmaf(-wg, u2, a2[i]);
            }
        }
#pragma unroll
        for (int j = 0; j < 16; j++) {
            float p3 = phi[(size_t)(mb + j) * 384 + 256 + f];
            v1[(size_t)(0 * NN + mb + j) * 128 + f] = p3 * a0[j];
            v1[(size_t)(1 * NN + mb + j) * 128 + f] = p3 * a1[j];
            v1[(size_t)(2 * NN + mb + j) * 128 + f] = p3 * a2[j];
        }
    }
}

// ---------------- x = [ ||Vv|| | s1 ] -----------------------------------------
__global__ void k_buildx(const float* __restrict__ Vv,
                         const float* __restrict__ s1,
                         float* __restrict__ x) {
    int i = blockIdx.x * 256 + threadIdx.x;
    int n = i >> 7, f = i & 127;
    float v0 = Vv[i];
    float v1 = Vv[(size_t)NN * 128 + i];
    float v2 = Vv[(size_t)2 * NN * 128 + i];
    x[(size_t)n * 256 + f]       = sqrtf(v0 * v0 + v1 * v1 + v2 * v2);
    x[(size_t)n * 256 + 128 + f] = s1[i];
}

// ---------------- final epilogue -----------------------------------------------
__global__ void k_final(const float* __restrict__ m,
                        const float* __restrict__ Uv,
                        const float* __restrict__ Vv,
                        float* __restrict__ out) {
    __shared__ float dvs[768];
    int t = threadIdx.x;
    int i = blockIdx.x * 256 + t;
    int n = i >> 7, f = i & 127;
    float avv = m[(size_t)n * 384 + f];
    float asv = m[(size_t)n * 384 + 128 + f];
    float ass = m[(size_t)n * 384 + 256 + f];
    float u0 = Uv[i], u1 = Uv[(size_t)NN * 128 + i], u2 = Uv[(size_t)2 * NN * 128 + i];
    float v0 = Vv[i], v1 = Vv[(size_t)NN * 128 + i], v2 = Vv[(size_t)2 * NN * 128 + i];
    out[i] = (u0 * v0 + u1 * v1 + u2 * v2) * asv + ass;
    dvs[t * 3 + 0] = avv * u0;
    dvs[t * 3 + 1] = avv * u1;
    dvs[t * 3 + 2] = avv * u2;
    __syncthreads();
    size_t base = (size_t)NN * 128 + (size_t)blockIdx.x * 768;
    out[base + t]       = dvs[t];
    out[base + 256 + t] = dvs[256 + t];
    out[base + 512 + t] = dvs[512 + t];
}

// ---------------- launch --------------------------------------------------------
extern "C" void kernel_launch(void* const* d_in, const int* in_sizes, int n_in,
                              void* d_out, int out_size) {
    const int*   atoms = (const int*)  d_in[0];
    const float* pos   = (const float*)d_in[1];
    const float* embed = (const float*)d_in[4];
    const float* w_s1  = (const float*)d_in[5];
    const float* b_s1  = (const float*)d_in[6];
    const float* w_s2  = (const float*)d_in[7];
    const float* b_s2  = (const float*)d_in[8];
    const float* w_r   = (const float*)d_in[9];
    const float* b_r   = (const float*)d_in[10];
    const float* w_u1  = (const float*)d_in[11];
    const float* b_u1  = (const float*)d_in[12];
    const float* w_u2  = (const float*)d_in[13];
    const float* b_u2  = (const float*)d_in[14];
    const float* Uw    = (const float*)d_in[15];
    const float* Ub    = (const float*)d_in[16];
    const float* Vw    = (const float*)d_in[17];
    const float* Vb    = (const float*)d_in[18];
    float* out = (float*)d_out;

    float *h, *phi, *s1, *v1, *Uv, *Vv, *x, *u, *mm;
    cudaGetSymbolAddress((void**)&h,   g_h);
    cudaGetSymbolAddress((void**)&phi, g_phi);
    cudaGetSymbolAddress((void**)&s1,  g_s1);
    cudaGetSymbolAddress((void**)&v1,  g_v1);
    cudaGetSymbolAddress((void**)&Uv,  g_Uv);
    cudaGetSymbolAddress((void**)&Vv,  g_Vv);
    cudaGetSymbolAddress((void**)&x,   g_x);
    cudaGetSymbolAddress((void**)&u,   g_u);
    cudaGetSymbolAddress((void**)&mm,  g_m);

    // 1) h = silu(embed[atoms] @ w_s1 + b_s1)
    k_gemm_tf32<<<dim3(NN / 128, 2), 128>>>(embed, atoms, w_s1, b_s1, h, 128, 128, 1);
    // 2) phi = h @ w_s2 + b_s2
    k_gemm_tf32<<<dim3(NN / 128, 6), 128>>>(h, nullptr, w_s2, b_s2, phi, 128, 384, 0);
    // 3) edge aggregation (one block per molecule)
    k_edge<<<NN / 16, 256>>>(pos, phi, w_r, b_r, s1, v1);
    // 4) six U/V plane GEMMs in one launch
    k_gemm_uv_tf32<<<dim3(NN / 128, 2, 6), 128>>>(v1, Uw, Ub, Vw, Vb, Uv, Vv);
    // 5) x = [ ||Vv|| | s1 ]
    k_buildx<<<NN * 128 / 256, 256>>>(Vv, s1, x);
    // 6) u = silu(x @ w_u1 + b_u1)
    k_gemm_tf32<<<dim3(NN / 128, 2), 128>>>(x, nullptr, w_u1, b_u1, u, 256, 128, 1);
    // 7) m = u @ w_u2 + b_u2
    k_gemm_tf32<<<dim3(NN / 128, 6), 128>>>(u, nullptr, w_u2, b_u2, mm, 128, 384, 0);
    // 8) epilogue
    k_final<<<NN * 128 / 256, 256>>>(mm, Uv, Vv, out);
}